// round 4
// baseline (speedup 1.0000x reference)
#include <cuda_runtime.h>
#include <cuda_bf16.h>

// PepEmbedding: out[b,h,:] = soft_threshold(emb[x[b,h],:], s[x[b,h],:])
//   soft_threshold(v,s) = sign(v)*relu(|v| - sigmoid(s))
//
// R4: bucket-major gather (duplicate indices hit L2: proven -24us on the
// gather) with the counting-sort overhead squeezed:
//   - scanB fused into scatter (redundant 256-wide smem scan per block)
//   - scatter groups keys by bucket in smem, then writes coalesced runs
//     (8B scattered stores -> ~32B contiguous runs, kills 4x write amp)

#define ROWS        (16384 * 50)     // 819,200
#define NBUCKETS    256
#define BUCKET_SHIFT 12              // idx >> 12 -> bucket 0..244
#define NBLK        800              // 819200 / 1024
#define VEC_PER_ROW 32               // 128 floats / float4

typedef unsigned long long ull;

// Scratch (device globals — allocation is forbidden)
__device__ int cnt[NBLK * NBUCKETS];   // per-block counts -> exclusive offsets
__device__ int bucket_total[NBUCKETS];
__device__ ull sorted_key[ROWS];       // (idx << 32) | row

// ---------------------------------------------------------------- 1) histogram
__global__ __launch_bounds__(1024)
void k_hist(const int* __restrict__ x) {
    __shared__ int h[NBUCKETS];
    if (threadIdx.x < NBUCKETS) h[threadIdx.x] = 0;
    __syncthreads();

    int row = blockIdx.x * 1024 + threadIdx.x;   // grid covers ROWS exactly
    int b = x[row] >> BUCKET_SHIFT;
    atomicAdd(&h[b], 1);                         // smem atomic, ~4/bucket
    __syncthreads();

    if (threadIdx.x < NBUCKETS)
        cnt[blockIdx.x * NBUCKETS + threadIdx.x] = h[threadIdx.x];   // coalesced
}

// ------------------------------------------------ 2) scan counts across blocks
// one block per bucket: exclusive scan over 800 block-counts (in place)
__global__ __launch_bounds__(1024)
void k_scanA() {
    int b = blockIdx.x;
    int g = threadIdx.x;
    __shared__ int tmp[1024];
    int v = (g < NBLK) ? cnt[g * NBUCKETS + b] : 0;
    tmp[g] = v;
    __syncthreads();
    for (int off = 1; off < 1024; off <<= 1) {
        int u = (g >= off) ? tmp[g - off] : 0;
        __syncthreads();
        tmp[g] += u;
        __syncthreads();
    }
    if (g < NBLK) cnt[g * NBUCKETS + b] = tmp[g] - v;   // exclusive
    if (g == NBLK - 1) bucket_total[b] = tmp[g];        // inclusive total
}

// --------------------------------------------- 3) scatter (+ fused base scan)
__global__ __launch_bounds__(1024)
void k_scatter(const int* __restrict__ x) {
    __shared__ int cnt_loc[NBUCKETS];   // block-local bucket counts
    __shared__ int loff[NBUCKETS];      // exclusive scan of cnt_loc (smem slots)
    __shared__ int gstart[NBUCKETS];    // global start for this block per bucket
    __shared__ int tA[NBUCKETS], tB[NBUCKETS];
    __shared__ ull keys[1024];
    __shared__ int gpos[1024];

    int t = threadIdx.x;
    if (t < NBUCKETS) cnt_loc[t] = 0;
    __syncthreads();

    int row = blockIdx.x * 1024 + t;
    int idx = x[row];
    int b   = idx >> BUCKET_SHIFT;
    int lr  = atomicAdd(&cnt_loc[b], 1);      // local rank within block-bucket
    __syncthreads();

    // Dual Hillis-Steele scan: tA = block-local counts, tB = global bucket totals.
    int myA = 0, myB = 0;
    if (t < NBUCKETS)                       { myA = cnt_loc[t];           tA[t] = myA; }
    if (t >= NBUCKETS && t < 2 * NBUCKETS)  { myB = bucket_total[t - NBUCKETS];
                                              tB[t - NBUCKETS] = myB; }
    __syncthreads();
    #pragma unroll
    for (int off = 1; off < NBUCKETS; off <<= 1) {
        int vA = (t < NBUCKETS && t >= off) ? tA[t - off] : 0;
        int vB = (t >= NBUCKETS && t < 2 * NBUCKETS && (t - NBUCKETS) >= off)
                 ? tB[t - NBUCKETS - off] : 0;
        __syncthreads();
        if (t < NBUCKETS)                      tA[t] += vA;
        if (t >= NBUCKETS && t < 2 * NBUCKETS) tB[t - NBUCKETS] += vB;
        __syncthreads();
    }
    if (t < NBUCKETS)                      loff[t] = tA[t] - myA;           // local excl
    if (t >= NBUCKETS && t < 2 * NBUCKETS) tB[t - NBUCKETS] -= myB;         // global excl
    __syncthreads();
    if (t < NBUCKETS)
        gstart[t] = tB[t] + cnt[blockIdx.x * NBUCKETS + t];                 // coalesced
    __syncthreads();

    // group keys by bucket in smem; record each slot's global position
    int slot = loff[b] + lr;
    keys[slot] = ((ull)(unsigned)idx << 32) | (unsigned)row;
    gpos[slot] = gstart[b] + lr;        // linear in lr -> consecutive per bucket
    __syncthreads();

    // coalesced-run write: consecutive slots in a bucket -> consecutive gpos
    sorted_key[gpos[t]] = keys[t];
}

// ---------------------------------------------------------------- 4) gather
__device__ __forceinline__ float soft_thresh(float v, float sv) {
    float t = __fdividef(1.0f, 1.0f + __expf(-sv));
    float m = fmaxf(fabsf(v) - t, 0.0f);
    return copysignf(m, v);
}

__global__ __launch_bounds__(256, 8)
void k_gather(const float4* __restrict__ emb,
              const float4* __restrict__ s,
              float4* __restrict__ out) {
    long long gid  = (long long)blockIdx.x * blockDim.x + threadIdx.x;
    long long work = gid >> 5;                 // one warp per gathered row
    int       comp = (int)(gid & 31);

    ull key = __ldg(&sorted_key[work]);        // warp-uniform broadcast
    long long row = (long long)(unsigned)(key & 0xffffffffu);
    long long idx = (long long)(key >> 32);

    long long off = idx * VEC_PER_ROW + comp;
    float4 v = __ldg(&emb[off]);
    float4 t = __ldg(&s[off]);

    float4 o;
    o.x = soft_thresh(v.x, t.x);
    o.y = soft_thresh(v.y, t.y);
    o.z = soft_thresh(v.z, t.z);
    o.w = soft_thresh(v.w, t.w);

    // streaming store: write-once stream must not evict bucket-resident rows
    __stcs(&out[row * VEC_PER_ROW + comp], o);
}

// ---------------------------------------------------------------- launch
extern "C" void kernel_launch(void* const* d_in, const int* in_sizes, int n_in,
                              void* d_out, int out_size) {
    const int*    x   = (const int*)d_in[0];
    const float4* emb = (const float4*)d_in[1];
    const float4* s   = (const float4*)d_in[2];
    float4*       out = (float4*)d_out;

    k_hist   <<<NBLK, 1024>>>(x);
    k_scanA  <<<NBUCKETS, 1024>>>();
    k_scatter<<<NBLK, 1024>>>(x);

    const long long total_vec = (long long)ROWS * VEC_PER_ROW;  // 26,214,400
    k_gather <<<(int)(total_vec / 256), 256>>>(emb, s, out);
}

// round 5
// speedup vs baseline: 1.1660x; 1.1660x over previous
#include <cuda_runtime.h>
#include <cuda_bf16.h>

// PepEmbedding: out[b,h,:] = soft_threshold(emb[x[b,h],:], s[x[b,h],:])
//   soft_threshold(v,s) = sign(v)*relu(|v| - sigmoid(s))
//
// R5: bucket-major gather (traffic proven at the 959MB compulsory floor) with
// MLP raised 2->4: one warp = two consecutive sorted rows, each thread issues
// 4 independent float4 loads behind one 16B key load. Binning pipeline
// unchanged from R4 (smem histograms, hierarchical scan, coalesced scatter).

#define ROWS        (16384 * 50)     // 819,200
#define NBUCKETS    256
#define BUCKET_SHIFT 12              // idx >> 12 -> bucket 0..244
#define NBLK        800              // 819200 / 1024
#define VEC_PER_ROW 32               // 128 floats / float4

typedef unsigned long long ull;

// Scratch (device globals — allocation is forbidden)
__device__ int cnt[NBLK * NBUCKETS];   // per-block counts -> exclusive offsets
__device__ int bucket_total[NBUCKETS];
__device__ ull sorted_key[ROWS];       // (idx << 32) | row

// ---------------------------------------------------------------- 1) histogram
__global__ __launch_bounds__(1024)
void k_hist(const int* __restrict__ x) {
    __shared__ int h[NBUCKETS];
    if (threadIdx.x < NBUCKETS) h[threadIdx.x] = 0;
    __syncthreads();

    int row = blockIdx.x * 1024 + threadIdx.x;
    int b = x[row] >> BUCKET_SHIFT;
    atomicAdd(&h[b], 1);
    __syncthreads();

    if (threadIdx.x < NBUCKETS)
        cnt[blockIdx.x * NBUCKETS + threadIdx.x] = h[threadIdx.x];
}

// ------------------------------------------------ 2) scan counts across blocks
__global__ __launch_bounds__(1024)
void k_scanA() {
    int b = blockIdx.x;
    int g = threadIdx.x;
    __shared__ int tmp[1024];
    int v = (g < NBLK) ? cnt[g * NBUCKETS + b] : 0;
    tmp[g] = v;
    __syncthreads();
    for (int off = 1; off < 1024; off <<= 1) {
        int u = (g >= off) ? tmp[g - off] : 0;
        __syncthreads();
        tmp[g] += u;
        __syncthreads();
    }
    if (g < NBLK) cnt[g * NBUCKETS + b] = tmp[g] - v;   // exclusive
    if (g == NBLK - 1) bucket_total[b] = tmp[g];        // inclusive total
}

// --------------------------------------------- 3) scatter (+ fused base scan)
__global__ __launch_bounds__(1024)
void k_scatter(const int* __restrict__ x) {
    __shared__ int cnt_loc[NBUCKETS];
    __shared__ int loff[NBUCKETS];
    __shared__ int gstart[NBUCKETS];
    __shared__ int tA[NBUCKETS], tB[NBUCKETS];
    __shared__ ull keys[1024];
    __shared__ int gpos[1024];

    int t = threadIdx.x;
    if (t < NBUCKETS) cnt_loc[t] = 0;
    __syncthreads();

    int row = blockIdx.x * 1024 + t;
    int idx = x[row];
    int b   = idx >> BUCKET_SHIFT;
    int lr  = atomicAdd(&cnt_loc[b], 1);
    __syncthreads();

    int myA = 0, myB = 0;
    if (t < NBUCKETS)                       { myA = cnt_loc[t];           tA[t] = myA; }
    if (t >= NBUCKETS && t < 2 * NBUCKETS)  { myB = bucket_total[t - NBUCKETS];
                                              tB[t - NBUCKETS] = myB; }
    __syncthreads();
    #pragma unroll
    for (int off = 1; off < NBUCKETS; off <<= 1) {
        int vA = (t < NBUCKETS && t >= off) ? tA[t - off] : 0;
        int vB = (t >= NBUCKETS && t < 2 * NBUCKETS && (t - NBUCKETS) >= off)
                 ? tB[t - NBUCKETS - off] : 0;
        __syncthreads();
        if (t < NBUCKETS)                      tA[t] += vA;
        if (t >= NBUCKETS && t < 2 * NBUCKETS) tB[t - NBUCKETS] += vB;
        __syncthreads();
    }
    if (t < NBUCKETS)                      loff[t] = tA[t] - myA;
    if (t >= NBUCKETS && t < 2 * NBUCKETS) tB[t - NBUCKETS] -= myB;
    __syncthreads();
    if (t < NBUCKETS)
        gstart[t] = tB[t] + cnt[blockIdx.x * NBUCKETS + t];
    __syncthreads();

    int slot = loff[b] + lr;
    keys[slot] = ((ull)(unsigned)idx << 32) | (unsigned)row;
    gpos[slot] = gstart[b] + lr;
    __syncthreads();

    sorted_key[gpos[t]] = keys[t];       // coalesced runs per bucket
}

// ---------------------------------------------------------------- 4) gather
__device__ __forceinline__ float soft_thresh(float v, float sv) {
    float t = __fdividef(1.0f, 1.0f + __expf(-sv));
    float m = fmaxf(fabsf(v) - t, 0.0f);
    return copysignf(m, v);
}

__global__ __launch_bounds__(256, 8)
void k_gather(const float4* __restrict__ emb,
              const float4* __restrict__ s,
              float4* __restrict__ out) {
    // one warp = TWO consecutive sorted rows -> 4 independent loads per thread
    long long gid  = (long long)blockIdx.x * blockDim.x + threadIdx.x;
    long long warp = gid >> 5;
    int       comp = (int)(gid & 31);

    ulonglong2 kk = __ldg((const ulonglong2*)&sorted_key[warp * 2]); // 16B uniform
    long long row0 = (long long)(unsigned)(kk.x & 0xffffffffu);
    long long idx0 = (long long)(kk.x >> 32);
    long long row1 = (long long)(unsigned)(kk.y & 0xffffffffu);
    long long idx1 = (long long)(kk.y >> 32);

    long long off0 = idx0 * VEC_PER_ROW + comp;
    long long off1 = idx1 * VEC_PER_ROW + comp;

    // 4 independent 16B loads issued back-to-back (MLP=4)
    float4 v0 = __ldg(&emb[off0]);
    float4 t0 = __ldg(&s[off0]);
    float4 v1 = __ldg(&emb[off1]);
    float4 t1 = __ldg(&s[off1]);

    float4 o0, o1;
    o0.x = soft_thresh(v0.x, t0.x);
    o0.y = soft_thresh(v0.y, t0.y);
    o0.z = soft_thresh(v0.z, t0.z);
    o0.w = soft_thresh(v0.w, t0.w);
    o1.x = soft_thresh(v1.x, t1.x);
    o1.y = soft_thresh(v1.y, t1.y);
    o1.z = soft_thresh(v1.z, t1.z);
    o1.w = soft_thresh(v1.w, t1.w);

    __stcs(&out[row0 * VEC_PER_ROW + comp], o0);
    __stcs(&out[row1 * VEC_PER_ROW + comp], o1);
}

// ---------------------------------------------------------------- launch
extern "C" void kernel_launch(void* const* d_in, const int* in_sizes, int n_in,
                              void* d_out, int out_size) {
    const int*    x   = (const int*)d_in[0];
    const float4* emb = (const float4*)d_in[1];
    const float4* s   = (const float4*)d_in[2];
    float4*       out = (float4*)d_out;

    k_hist   <<<NBLK, 1024>>>(x);
    k_scanA  <<<NBUCKETS, 1024>>>();
    k_scatter<<<NBLK, 1024>>>(x);

    // ROWS/2 warps, 8 warps per 256-thread block
    const int blocks = ROWS / 16;             // 51,200
    k_gather <<<blocks, 256>>>(emb, s, out);
}

// round 6
// speedup vs baseline: 1.1689x; 1.0025x over previous
#include <cuda_runtime.h>
#include <cuda_bf16.h>

// PepEmbedding: out[b,h,:] = soft_threshold(emb[x[b,h],:], s[x[b,h],:])
//   soft_threshold(v,s) = sign(v)*relu(|v| - sigmoid(s))
//
// R5: bucket-major gather (traffic proven at the 959MB compulsory floor) with
// MLP raised 2->4: one warp = two consecutive sorted rows, each thread issues
// 4 independent float4 loads behind one 16B key load. Binning pipeline
// unchanged from R4 (smem histograms, hierarchical scan, coalesced scatter).

#define ROWS        (16384 * 50)     // 819,200
#define NBUCKETS    256
#define BUCKET_SHIFT 12              // idx >> 12 -> bucket 0..244
#define NBLK        800              // 819200 / 1024
#define VEC_PER_ROW 32               // 128 floats / float4

typedef unsigned long long ull;

// Scratch (device globals — allocation is forbidden)
__device__ int cnt[NBLK * NBUCKETS];   // per-block counts -> exclusive offsets
__device__ int bucket_total[NBUCKETS];
__device__ ull sorted_key[ROWS];       // (idx << 32) | row

// ---------------------------------------------------------------- 1) histogram
__global__ __launch_bounds__(1024)
void k_hist(const int* __restrict__ x) {
    __shared__ int h[NBUCKETS];
    if (threadIdx.x < NBUCKETS) h[threadIdx.x] = 0;
    __syncthreads();

    int row = blockIdx.x * 1024 + threadIdx.x;
    int b = x[row] >> BUCKET_SHIFT;
    atomicAdd(&h[b], 1);
    __syncthreads();

    if (threadIdx.x < NBUCKETS)
        cnt[blockIdx.x * NBUCKETS + threadIdx.x] = h[threadIdx.x];
}

// ------------------------------------------------ 2) scan counts across blocks
__global__ __launch_bounds__(1024)
void k_scanA() {
    int b = blockIdx.x;
    int g = threadIdx.x;
    __shared__ int tmp[1024];
    int v = (g < NBLK) ? cnt[g * NBUCKETS + b] : 0;
    tmp[g] = v;
    __syncthreads();
    for (int off = 1; off < 1024; off <<= 1) {
        int u = (g >= off) ? tmp[g - off] : 0;
        __syncthreads();
        tmp[g] += u;
        __syncthreads();
    }
    if (g < NBLK) cnt[g * NBUCKETS + b] = tmp[g] - v;   // exclusive
    if (g == NBLK - 1) bucket_total[b] = tmp[g];        // inclusive total
}

// --------------------------------------------- 3) scatter (+ fused base scan)
__global__ __launch_bounds__(1024)
void k_scatter(const int* __restrict__ x) {
    __shared__ int cnt_loc[NBUCKETS];
    __shared__ int loff[NBUCKETS];
    __shared__ int gstart[NBUCKETS];
    __shared__ int tA[NBUCKETS], tB[NBUCKETS];
    __shared__ ull keys[1024];
    __shared__ int gpos[1024];

    int t = threadIdx.x;
    if (t < NBUCKETS) cnt_loc[t] = 0;
    __syncthreads();

    int row = blockIdx.x * 1024 + t;
    int idx = x[row];
    int b   = idx >> BUCKET_SHIFT;
    int lr  = atomicAdd(&cnt_loc[b], 1);
    __syncthreads();

    int myA = 0, myB = 0;
    if (t < NBUCKETS)                       { myA = cnt_loc[t];           tA[t] = myA; }
    if (t >= NBUCKETS && t < 2 * NBUCKETS)  { myB = bucket_total[t - NBUCKETS];
                                              tB[t - NBUCKETS] = myB; }
    __syncthreads();
    #pragma unroll
    for (int off = 1; off < NBUCKETS; off <<= 1) {
        int vA = (t < NBUCKETS && t >= off) ? tA[t - off] : 0;
        int vB = (t >= NBUCKETS && t < 2 * NBUCKETS && (t - NBUCKETS) >= off)
                 ? tB[t - NBUCKETS - off] : 0;
        __syncthreads();
        if (t < NBUCKETS)                      tA[t] += vA;
        if (t >= NBUCKETS && t < 2 * NBUCKETS) tB[t - NBUCKETS] += vB;
        __syncthreads();
    }
    if (t < NBUCKETS)                      loff[t] = tA[t] - myA;
    if (t >= NBUCKETS && t < 2 * NBUCKETS) tB[t - NBUCKETS] -= myB;
    __syncthreads();
    if (t < NBUCKETS)
        gstart[t] = tB[t] + cnt[blockIdx.x * NBUCKETS + t];
    __syncthreads();

    int slot = loff[b] + lr;
    keys[slot] = ((ull)(unsigned)idx << 32) | (unsigned)row;
    gpos[slot] = gstart[b] + lr;
    __syncthreads();

    sorted_key[gpos[t]] = keys[t];       // coalesced runs per bucket
}

// ---------------------------------------------------------------- 4) gather
__device__ __forceinline__ float soft_thresh(float v, float sv) {
    float t = __fdividef(1.0f, 1.0f + __expf(-sv));
    float m = fmaxf(fabsf(v) - t, 0.0f);
    return copysignf(m, v);
}

__global__ __launch_bounds__(256, 8)
void k_gather(const float4* __restrict__ emb,
              const float4* __restrict__ s,
              float4* __restrict__ out) {
    // one warp = TWO consecutive sorted rows -> 4 independent loads per thread
    long long gid  = (long long)blockIdx.x * blockDim.x + threadIdx.x;
    long long warp = gid >> 5;
    int       comp = (int)(gid & 31);

    ulonglong2 kk = __ldg((const ulonglong2*)&sorted_key[warp * 2]); // 16B uniform
    long long row0 = (long long)(unsigned)(kk.x & 0xffffffffu);
    long long idx0 = (long long)(kk.x >> 32);
    long long row1 = (long long)(unsigned)(kk.y & 0xffffffffu);
    long long idx1 = (long long)(kk.y >> 32);

    long long off0 = idx0 * VEC_PER_ROW + comp;
    long long off1 = idx1 * VEC_PER_ROW + comp;

    // 4 independent 16B loads issued back-to-back (MLP=4)
    float4 v0 = __ldg(&emb[off0]);
    float4 t0 = __ldg(&s[off0]);
    float4 v1 = __ldg(&emb[off1]);
    float4 t1 = __ldg(&s[off1]);

    float4 o0, o1;
    o0.x = soft_thresh(v0.x, t0.x);
    o0.y = soft_thresh(v0.y, t0.y);
    o0.z = soft_thresh(v0.z, t0.z);
    o0.w = soft_thresh(v0.w, t0.w);
    o1.x = soft_thresh(v1.x, t1.x);
    o1.y = soft_thresh(v1.y, t1.y);
    o1.z = soft_thresh(v1.z, t1.z);
    o1.w = soft_thresh(v1.w, t1.w);

    __stcs(&out[row0 * VEC_PER_ROW + comp], o0);
    __stcs(&out[row1 * VEC_PER_ROW + comp], o1);
}

// ---------------------------------------------------------------- launch
extern "C" void kernel_launch(void* const* d_in, const int* in_sizes, int n_in,
                              void* d_out, int out_size) {
    const int*    x   = (const int*)d_in[0];
    const float4* emb = (const float4*)d_in[1];
    const float4* s   = (const float4*)d_in[2];
    float4*       out = (float4*)d_out;

    k_hist   <<<NBLK, 1024>>>(x);
    k_scanA  <<<NBUCKETS, 1024>>>();
    k_scatter<<<NBLK, 1024>>>(x);

    // ROWS/2 warps, 8 warps per 256-thread block
    const int blocks = ROWS / 16;             // 51,200
    k_gather <<<blocks, 256>>>(emb, s, out);
}

// round 7
// speedup vs baseline: 1.2100x; 1.0352x over previous
#include <cuda_runtime.h>
#include <cuda_bf16.h>

// PepEmbedding: out[b,h,:] = soft_threshold(emb[x[b,h],:], s[x[b,h],:])
//   soft_threshold(v,s) = sign(v)*relu(|v| - sigmoid(s))
//
// R7: bucket-major gather at the 956MB compulsory-traffic floor.
//  - gather MLP 4->8: one warp = 4 consecutive sorted rows, 8 independent
//    float4 loads per thread (R5's MLP 2->4 gave 176->142us; push further)
//  - binning fixed costs halved: 400 blocks x 2048 rows (fewer scans/syncs,
//    half the cnt traffic, scanA width 800->400)

#define ROWS        (16384 * 50)     // 819,200
#define NBUCKETS    256
#define BUCKET_SHIFT 12              // idx >> 12 -> bucket 0..244
#define NBLK        400              // 819200 / 2048
#define RPB         2048             // rows per binning block
#define VEC_PER_ROW 32               // 128 floats / float4

typedef unsigned long long ull;

// Scratch (device globals — allocation is forbidden)
__device__ int cnt[NBLK * NBUCKETS];   // per-block counts -> exclusive offsets
__device__ int bucket_total[NBUCKETS];
__device__ ull sorted_key[ROWS];       // (idx << 32) | row

// ---------------------------------------------------------------- 1) histogram
__global__ __launch_bounds__(1024)
void k_hist(const int* __restrict__ x) {
    __shared__ int h[NBUCKETS];
    if (threadIdx.x < NBUCKETS) h[threadIdx.x] = 0;
    __syncthreads();

    int base = blockIdx.x * RPB;
    int b0 = x[base + threadIdx.x] >> BUCKET_SHIFT;
    int b1 = x[base + 1024 + threadIdx.x] >> BUCKET_SHIFT;
    atomicAdd(&h[b0], 1);
    atomicAdd(&h[b1], 1);
    __syncthreads();

    if (threadIdx.x < NBUCKETS)
        cnt[blockIdx.x * NBUCKETS + threadIdx.x] = h[threadIdx.x];
}

// ------------------------------------------------ 2) scan counts across blocks
__global__ __launch_bounds__(512)
void k_scanA() {
    int b = blockIdx.x;
    int g = threadIdx.x;
    __shared__ int tmp[512];
    int v = (g < NBLK) ? cnt[g * NBUCKETS + b] : 0;
    tmp[g] = v;
    __syncthreads();
    for (int off = 1; off < 512; off <<= 1) {
        int u = (g >= off) ? tmp[g - off] : 0;
        __syncthreads();
        tmp[g] += u;
        __syncthreads();
    }
    if (g < NBLK) cnt[g * NBUCKETS + b] = tmp[g] - v;   // exclusive
    if (g == NBLK - 1) bucket_total[b] = tmp[g];        // inclusive total
}

// --------------------------------------------- 3) scatter (+ fused base scan)
__global__ __launch_bounds__(1024)
void k_scatter(const int* __restrict__ x) {
    __shared__ int cnt_loc[NBUCKETS];
    __shared__ int loff[NBUCKETS];
    __shared__ int gstart[NBUCKETS];
    __shared__ int tA[NBUCKETS], tB[NBUCKETS];
    __shared__ ull keys[RPB];
    __shared__ int gpos[RPB];

    int t = threadIdx.x;
    if (t < NBUCKETS) cnt_loc[t] = 0;
    __syncthreads();

    int base = blockIdx.x * RPB;
    int row0 = base + t;
    int row1 = base + 1024 + t;
    int idx0 = x[row0];
    int idx1 = x[row1];
    int b0 = idx0 >> BUCKET_SHIFT;
    int b1 = idx1 >> BUCKET_SHIFT;
    int lr0 = atomicAdd(&cnt_loc[b0], 1);
    int lr1 = atomicAdd(&cnt_loc[b1], 1);
    __syncthreads();

    // Dual Hillis-Steele scan: tA = block-local counts, tB = global totals.
    int myA = 0, myB = 0;
    if (t < NBUCKETS)                       { myA = cnt_loc[t];           tA[t] = myA; }
    if (t >= NBUCKETS && t < 2 * NBUCKETS)  { myB = bucket_total[t - NBUCKETS];
                                              tB[t - NBUCKETS] = myB; }
    __syncthreads();
    #pragma unroll
    for (int off = 1; off < NBUCKETS; off <<= 1) {
        int vA = (t < NBUCKETS && t >= off) ? tA[t - off] : 0;
        int vB = (t >= NBUCKETS && t < 2 * NBUCKETS && (t - NBUCKETS) >= off)
                 ? tB[t - NBUCKETS - off] : 0;
        __syncthreads();
        if (t < NBUCKETS)                      tA[t] += vA;
        if (t >= NBUCKETS && t < 2 * NBUCKETS) tB[t - NBUCKETS] += vB;
        __syncthreads();
    }
    if (t < NBUCKETS)                      loff[t] = tA[t] - myA;
    if (t >= NBUCKETS && t < 2 * NBUCKETS) tB[t - NBUCKETS] -= myB;
    __syncthreads();
    if (t < NBUCKETS)
        gstart[t] = tB[t] + cnt[blockIdx.x * NBUCKETS + t];
    __syncthreads();

    // group keys by bucket in smem, record final global positions
    int s0 = loff[b0] + lr0;
    int s1 = loff[b1] + lr1;
    keys[s0] = ((ull)(unsigned)idx0 << 32) | (unsigned)row0;
    gpos[s0] = gstart[b0] + lr0;
    keys[s1] = ((ull)(unsigned)idx1 << 32) | (unsigned)row1;
    gpos[s1] = gstart[b1] + lr1;
    __syncthreads();

    // coalesced-run writes (consecutive slots per bucket -> consecutive gpos)
    sorted_key[gpos[t]]        = keys[t];
    sorted_key[gpos[t + 1024]] = keys[t + 1024];
}

// ---------------------------------------------------------------- 4) gather
__device__ __forceinline__ float soft_thresh(float v, float sv) {
    float t = __fdividef(1.0f, 1.0f + __expf(-sv));
    float m = fmaxf(fabsf(v) - t, 0.0f);
    return copysignf(m, v);
}

__device__ __forceinline__ float4 soft_thresh4(float4 v, float4 t) {
    float4 o;
    o.x = soft_thresh(v.x, t.x);
    o.y = soft_thresh(v.y, t.y);
    o.z = soft_thresh(v.z, t.z);
    o.w = soft_thresh(v.w, t.w);
    return o;
}

__global__ __launch_bounds__(256, 4)
void k_gather(const float4* __restrict__ emb,
              const float4* __restrict__ s,
              float4* __restrict__ out) {
    // one warp = FOUR consecutive sorted rows -> 8 independent loads / thread
    long long gid  = (long long)blockIdx.x * blockDim.x + threadIdx.x;
    long long warp = gid >> 5;
    int       comp = (int)(gid & 31);

    const ulonglong2* kp = (const ulonglong2*)&sorted_key[warp * 4];
    ulonglong2 kA = __ldg(&kp[0]);     // 32B warp-uniform key block
    ulonglong2 kB = __ldg(&kp[1]);

    long long off0 = (long long)(kA.x >> 32) * VEC_PER_ROW + comp;
    long long off1 = (long long)(kA.y >> 32) * VEC_PER_ROW + comp;
    long long off2 = (long long)(kB.x >> 32) * VEC_PER_ROW + comp;
    long long off3 = (long long)(kB.y >> 32) * VEC_PER_ROW + comp;

    // 8 independent 16B loads in flight (MLP=8)
    float4 v0 = __ldg(&emb[off0]);
    float4 v1 = __ldg(&emb[off1]);
    float4 v2 = __ldg(&emb[off2]);
    float4 v3 = __ldg(&emb[off3]);
    float4 t0 = __ldg(&s[off0]);
    float4 t1 = __ldg(&s[off1]);
    float4 t2 = __ldg(&s[off2]);
    float4 t3 = __ldg(&s[off3]);

    long long r0 = (long long)(unsigned)(kA.x & 0xffffffffu) * VEC_PER_ROW + comp;
    long long r1 = (long long)(unsigned)(kA.y & 0xffffffffu) * VEC_PER_ROW + comp;
    long long r2 = (long long)(unsigned)(kB.x & 0xffffffffu) * VEC_PER_ROW + comp;
    long long r3 = (long long)(unsigned)(kB.y & 0xffffffffu) * VEC_PER_ROW + comp;

    __stcs(&out[r0], soft_thresh4(v0, t0));
    __stcs(&out[r1], soft_thresh4(v1, t1));
    __stcs(&out[r2], soft_thresh4(v2, t2));
    __stcs(&out[r3], soft_thresh4(v3, t3));
}

// ---------------------------------------------------------------- launch
extern "C" void kernel_launch(void* const* d_in, const int* in_sizes, int n_in,
                              void* d_out, int out_size) {
    const int*    x   = (const int*)d_in[0];
    const float4* emb = (const float4*)d_in[1];
    const float4* s   = (const float4*)d_in[2];
    float4*       out = (float4*)d_out;

    k_hist   <<<NBLK, 1024>>>(x);
    k_scanA  <<<NBUCKETS, 512>>>();
    k_scatter<<<NBLK, 1024>>>(x);

    // ROWS/4 warps, 8 warps per 256-thread block
    const int blocks = ROWS / 32;             // 25,600
    k_gather <<<blocks, 256>>>(emb, s, out);
}

// round 9
// speedup vs baseline: 1.2124x; 1.0020x over previous
#include <cuda_runtime.h>
#include <cuda_bf16.h>

// PepEmbedding: out[b,h,:] = soft_threshold(emb[x[b,h],:], s[x[b,h],:])
//   soft_threshold(v,s) = sign(v)*relu(|v| - sigmoid(s))
//
// R9 = recombination of proven-best components:
//  - R7 binning (smem hist + hierarchical scan + coalesced scatter), ~18.6us
//  - R6 gather (MLP=4: one warp = 2 sorted rows), 142.4us @ 84.7% DRAM
//  - gather offsets in 32-bit unsigned (max 26.2M) to kill 64-bit IMAD chains
// (R8's fused atomic-reservation sort produced corrupt keys -> reverted.)

#define ROWS        (16384 * 50)     // 819,200
#define NBUCKETS    256
#define BUCKET_SHIFT 12              // idx >> 12 -> bucket 0..244
#define NBLK        400              // 819200 / 2048
#define RPB         2048             // rows per binning block
#define VEC_PER_ROW 32               // 128 floats / float4

typedef unsigned long long ull;

// Scratch (device globals — allocation is forbidden)
__device__ int cnt[NBLK * NBUCKETS];   // per-block counts -> exclusive offsets
__device__ int bucket_total[NBUCKETS];
__device__ ull sorted_key[ROWS];       // (idx << 32) | row

// ---------------------------------------------------------------- 1) histogram
__global__ __launch_bounds__(1024)
void k_hist(const int* __restrict__ x) {
    __shared__ int h[NBUCKETS];
    if (threadIdx.x < NBUCKETS) h[threadIdx.x] = 0;
    __syncthreads();

    int base = blockIdx.x * RPB;
    int b0 = x[base + threadIdx.x] >> BUCKET_SHIFT;
    int b1 = x[base + 1024 + threadIdx.x] >> BUCKET_SHIFT;
    atomicAdd(&h[b0], 1);
    atomicAdd(&h[b1], 1);
    __syncthreads();

    if (threadIdx.x < NBUCKETS)
        cnt[blockIdx.x * NBUCKETS + threadIdx.x] = h[threadIdx.x];
}

// ------------------------------------------------ 2) scan counts across blocks
__global__ __launch_bounds__(512)
void k_scanA() {
    int b = blockIdx.x;
    int g = threadIdx.x;
    __shared__ int tmp[512];
    int v = (g < NBLK) ? cnt[g * NBUCKETS + b] : 0;
    tmp[g] = v;
    __syncthreads();
    for (int off = 1; off < 512; off <<= 1) {
        int u = (g >= off) ? tmp[g - off] : 0;
        __syncthreads();
        tmp[g] += u;
        __syncthreads();
    }
    if (g < NBLK) cnt[g * NBUCKETS + b] = tmp[g] - v;   // exclusive
    if (g == NBLK - 1) bucket_total[b] = tmp[g];        // inclusive total
}

// --------------------------------------------- 3) scatter (+ fused base scan)
__global__ __launch_bounds__(1024)
void k_scatter(const int* __restrict__ x) {
    __shared__ int cnt_loc[NBUCKETS];
    __shared__ int loff[NBUCKETS];
    __shared__ int gstart[NBUCKETS];
    __shared__ int tA[NBUCKETS], tB[NBUCKETS];
    __shared__ ull keys[RPB];
    __shared__ int gpos[RPB];

    int t = threadIdx.x;
    if (t < NBUCKETS) cnt_loc[t] = 0;
    __syncthreads();

    int base = blockIdx.x * RPB;
    int row0 = base + t;
    int row1 = base + 1024 + t;
    int idx0 = x[row0];
    int idx1 = x[row1];
    int b0 = idx0 >> BUCKET_SHIFT;
    int b1 = idx1 >> BUCKET_SHIFT;
    int lr0 = atomicAdd(&cnt_loc[b0], 1);
    int lr1 = atomicAdd(&cnt_loc[b1], 1);
    __syncthreads();

    // Dual Hillis-Steele scan: tA = block-local counts, tB = global totals.
    int myA = 0, myB = 0;
    if (t < NBUCKETS)                       { myA = cnt_loc[t];           tA[t] = myA; }
    if (t >= NBUCKETS && t < 2 * NBUCKETS)  { myB = bucket_total[t - NBUCKETS];
                                              tB[t - NBUCKETS] = myB; }
    __syncthreads();
    #pragma unroll
    for (int off = 1; off < NBUCKETS; off <<= 1) {
        int vA = (t < NBUCKETS && t >= off) ? tA[t - off] : 0;
        int vB = (t >= NBUCKETS && t < 2 * NBUCKETS && (t - NBUCKETS) >= off)
                 ? tB[t - NBUCKETS - off] : 0;
        __syncthreads();
        if (t < NBUCKETS)                      tA[t] += vA;
        if (t >= NBUCKETS && t < 2 * NBUCKETS) tB[t - NBUCKETS] += vB;
        __syncthreads();
    }
    if (t < NBUCKETS)                      loff[t] = tA[t] - myA;
    if (t >= NBUCKETS && t < 2 * NBUCKETS) tB[t - NBUCKETS] -= myB;
    __syncthreads();
    if (t < NBUCKETS)
        gstart[t] = tB[t] + cnt[blockIdx.x * NBUCKETS + t];
    __syncthreads();

    int s0 = loff[b0] + lr0;
    int s1 = loff[b1] + lr1;
    keys[s0] = ((ull)(unsigned)idx0 << 32) | (unsigned)row0;
    gpos[s0] = gstart[b0] + lr0;
    keys[s1] = ((ull)(unsigned)idx1 << 32) | (unsigned)row1;
    gpos[s1] = gstart[b1] + lr1;
    __syncthreads();

    sorted_key[gpos[t]]        = keys[t];       // coalesced runs per bucket
    sorted_key[gpos[t + 1024]] = keys[t + 1024];
}

// ---------------------------------------------------------------- 4) gather
__device__ __forceinline__ float soft_thresh(float v, float sv) {
    float t = __fdividef(1.0f, 1.0f + __expf(-sv));
    float m = fmaxf(fabsf(v) - t, 0.0f);
    return copysignf(m, v);
}

__device__ __forceinline__ float4 soft_thresh4(float4 v, float4 t) {
    float4 o;
    o.x = soft_thresh(v.x, t.x);
    o.y = soft_thresh(v.y, t.y);
    o.z = soft_thresh(v.z, t.z);
    o.w = soft_thresh(v.w, t.w);
    return o;
}

__global__ __launch_bounds__(256, 8)
void k_gather(const float4* __restrict__ emb,
              const float4* __restrict__ s,
              float4* __restrict__ out) {
    // one warp = TWO consecutive sorted rows -> 4 independent loads per thread
    unsigned gid  = blockIdx.x * 256u + threadIdx.x;
    unsigned warp = gid >> 5;
    unsigned comp = gid & 31u;

    ulonglong2 kk = __ldg((const ulonglong2*)&sorted_key[warp * 2]); // uniform
    // 32-bit offsets: max idx*32+31 = 32,000,031 and max row*32+31 = 26,214,399
    unsigned row0 = (unsigned)(kk.x & 0xffffffffu);
    unsigned idx0 = (unsigned)(kk.x >> 32);
    unsigned row1 = (unsigned)(kk.y & 0xffffffffu);
    unsigned idx1 = (unsigned)(kk.y >> 32);

    unsigned off0 = idx0 * (unsigned)VEC_PER_ROW + comp;
    unsigned off1 = idx1 * (unsigned)VEC_PER_ROW + comp;

    // 4 independent 16B loads in flight (MLP=4 — measured sweet spot)
    float4 v0 = __ldg(&emb[off0]);
    float4 t0 = __ldg(&s[off0]);
    float4 v1 = __ldg(&emb[off1]);
    float4 t1 = __ldg(&s[off1]);

    __stcs(&out[row0 * (unsigned)VEC_PER_ROW + comp], soft_thresh4(v0, t0));
    __stcs(&out[row1 * (unsigned)VEC_PER_ROW + comp], soft_thresh4(v1, t1));
}

// ---------------------------------------------------------------- launch
extern "C" void kernel_launch(void* const* d_in, const int* in_sizes, int n_in,
                              void* d_out, int out_size) {
    const int*    x   = (const int*)d_in[0];
    const float4* emb = (const float4*)d_in[1];
    const float4* s   = (const float4*)d_in[2];
    float4*       out = (float4*)d_out;

    k_hist   <<<NBLK, 1024>>>(x);
    k_scanA  <<<NBUCKETS, 512>>>();
    k_scatter<<<NBLK, 1024>>>(x);

    // ROWS/2 warps, 8 warps per 256-thread block
    k_gather<<<ROWS / 16, 256>>>(emb, s, out);
}

// round 10
// speedup vs baseline: 1.2192x; 1.0056x over previous
#include <cuda_runtime.h>
#include <cuda_bf16.h>

// PepEmbedding: out[b,h,:] = soft_threshold(emb[x[b,h],:], s[x[b,h],:])
//   soft_threshold(v,s) = sign(v)*relu(|v| - sigmoid(s))
//
// R10: gather untouched (MLP=4, 32-bit offsets — pinned at the ~85%-DRAM /
// 956MB compulsory floor). Binning widened: 200 blocks x 4096 rows, int4
// index loads, 4 rows/thread -> per-block scan/sync/launch overheads halved.

#define ROWS        (16384 * 50)     // 819,200
#define NBUCKETS    256
#define BUCKET_SHIFT 12              // idx >> 12 -> bucket 0..244
#define NBLK        200              // 819200 / 4096
#define RPB         4096             // rows per binning block
#define VEC_PER_ROW 32               // 128 floats / float4

typedef unsigned long long ull;

// Scratch (device globals — allocation is forbidden)
__device__ int cnt[NBLK * NBUCKETS];   // per-block counts -> exclusive offsets
__device__ int bucket_total[NBUCKETS];
__device__ ull sorted_key[ROWS];       // (idx << 32) | row

// ---------------------------------------------------------------- 1) histogram
__global__ __launch_bounds__(1024)
void k_hist(const int4* __restrict__ x4) {
    __shared__ int h[NBUCKETS];
    if (threadIdx.x < NBUCKETS) h[threadIdx.x] = 0;
    __syncthreads();

    int4 v = x4[blockIdx.x * 1024 + threadIdx.x];   // 4 indices, coalesced 16B
    atomicAdd(&h[v.x >> BUCKET_SHIFT], 1);
    atomicAdd(&h[v.y >> BUCKET_SHIFT], 1);
    atomicAdd(&h[v.z >> BUCKET_SHIFT], 1);
    atomicAdd(&h[v.w >> BUCKET_SHIFT], 1);
    __syncthreads();

    if (threadIdx.x < NBUCKETS)
        cnt[blockIdx.x * NBUCKETS + threadIdx.x] = h[threadIdx.x];
}

// ------------------------------------------------ 2) scan counts across blocks
__global__ __launch_bounds__(256)
void k_scanA() {
    int b = blockIdx.x;
    int g = threadIdx.x;
    __shared__ int tmp[256];
    int v = (g < NBLK) ? cnt[g * NBUCKETS + b] : 0;
    tmp[g] = v;
    __syncthreads();
    for (int off = 1; off < 256; off <<= 1) {
        int u = (g >= off) ? tmp[g - off] : 0;
        __syncthreads();
        tmp[g] += u;
        __syncthreads();
    }
    if (g < NBLK) cnt[g * NBUCKETS + b] = tmp[g] - v;   // exclusive
    if (g == NBLK - 1) bucket_total[b] = tmp[g];        // inclusive total
}

// --------------------------------------------- 3) scatter (+ fused base scan)
__global__ __launch_bounds__(1024)
void k_scatter(const int4* __restrict__ x4) {
    __shared__ int cnt_loc[NBUCKETS];
    __shared__ int loff[NBUCKETS];
    __shared__ int gstart[NBUCKETS];
    __shared__ int tA[NBUCKETS], tB[NBUCKETS];
    __shared__ ull keys[RPB];          // 32 KB
    __shared__ int gpos[RPB];          // 16 KB

    int t = threadIdx.x;
    if (t < NBUCKETS) cnt_loc[t] = 0;
    __syncthreads();

    int base = blockIdx.x * RPB;
    int4 v = x4[blockIdx.x * 1024 + t];          // rows base+4t .. base+4t+3
    int idx0 = v.x, idx1 = v.y, idx2 = v.z, idx3 = v.w;
    int b0 = idx0 >> BUCKET_SHIFT;
    int b1 = idx1 >> BUCKET_SHIFT;
    int b2 = idx2 >> BUCKET_SHIFT;
    int b3 = idx3 >> BUCKET_SHIFT;
    int lr0 = atomicAdd(&cnt_loc[b0], 1);
    int lr1 = atomicAdd(&cnt_loc[b1], 1);
    int lr2 = atomicAdd(&cnt_loc[b2], 1);
    int lr3 = atomicAdd(&cnt_loc[b3], 1);
    __syncthreads();

    // Dual Hillis-Steele scan: tA = block-local counts, tB = global totals.
    int myA = 0, myB = 0;
    if (t < NBUCKETS)                       { myA = cnt_loc[t];           tA[t] = myA; }
    if (t >= NBUCKETS && t < 2 * NBUCKETS)  { myB = bucket_total[t - NBUCKETS];
                                              tB[t - NBUCKETS] = myB; }
    __syncthreads();
    #pragma unroll
    for (int off = 1; off < NBUCKETS; off <<= 1) {
        int vA = (t < NBUCKETS && t >= off) ? tA[t - off] : 0;
        int vB = (t >= NBUCKETS && t < 2 * NBUCKETS && (t - NBUCKETS) >= off)
                 ? tB[t - NBUCKETS - off] : 0;
        __syncthreads();
        if (t < NBUCKETS)                      tA[t] += vA;
        if (t >= NBUCKETS && t < 2 * NBUCKETS) tB[t - NBUCKETS] += vB;
        __syncthreads();
    }
    if (t < NBUCKETS)                      loff[t] = tA[t] - myA;
    if (t >= NBUCKETS && t < 2 * NBUCKETS) tB[t - NBUCKETS] -= myB;
    __syncthreads();
    if (t < NBUCKETS)
        gstart[t] = tB[t] + cnt[blockIdx.x * NBUCKETS + t];
    __syncthreads();

    // group keys by bucket in smem; record final global positions
    int r = base + 4 * t;
    int s0 = loff[b0] + lr0;
    int s1 = loff[b1] + lr1;
    int s2 = loff[b2] + lr2;
    int s3 = loff[b3] + lr3;
    keys[s0] = ((ull)(unsigned)idx0 << 32) | (unsigned)(r + 0);
    keys[s1] = ((ull)(unsigned)idx1 << 32) | (unsigned)(r + 1);
    keys[s2] = ((ull)(unsigned)idx2 << 32) | (unsigned)(r + 2);
    keys[s3] = ((ull)(unsigned)idx3 << 32) | (unsigned)(r + 3);
    gpos[s0] = gstart[b0] + lr0;
    gpos[s1] = gstart[b1] + lr1;
    gpos[s2] = gstart[b2] + lr2;
    gpos[s3] = gstart[b3] + lr3;
    __syncthreads();

    // coalesced-run writes: consecutive slots per bucket -> consecutive gpos
    #pragma unroll
    for (int k = 0; k < 4; k++)
        sorted_key[gpos[t + k * 1024]] = keys[t + k * 1024];
}

// ---------------------------------------------------------------- 4) gather
__device__ __forceinline__ float soft_thresh(float v, float sv) {
    float t = __fdividef(1.0f, 1.0f + __expf(-sv));
    float m = fmaxf(fabsf(v) - t, 0.0f);
    return copysignf(m, v);
}

__device__ __forceinline__ float4 soft_thresh4(float4 v, float4 t) {
    float4 o;
    o.x = soft_thresh(v.x, t.x);
    o.y = soft_thresh(v.y, t.y);
    o.z = soft_thresh(v.z, t.z);
    o.w = soft_thresh(v.w, t.w);
    return o;
}

__global__ __launch_bounds__(256, 8)
void k_gather(const float4* __restrict__ emb,
              const float4* __restrict__ s,
              float4* __restrict__ out) {
    // one warp = TWO consecutive sorted rows -> 4 independent loads per thread
    unsigned gid  = blockIdx.x * 256u + threadIdx.x;
    unsigned warp = gid >> 5;
    unsigned comp = gid & 31u;

    ulonglong2 kk = __ldg((const ulonglong2*)&sorted_key[warp * 2]); // uniform
    unsigned row0 = (unsigned)(kk.x & 0xffffffffu);
    unsigned idx0 = (unsigned)(kk.x >> 32);
    unsigned row1 = (unsigned)(kk.y & 0xffffffffu);
    unsigned idx1 = (unsigned)(kk.y >> 32);

    unsigned off0 = idx0 * (unsigned)VEC_PER_ROW + comp;
    unsigned off1 = idx1 * (unsigned)VEC_PER_ROW + comp;

    // 4 independent 16B loads in flight (MLP=4 — measured sweet spot)
    float4 v0 = __ldg(&emb[off0]);
    float4 t0 = __ldg(&s[off0]);
    float4 v1 = __ldg(&emb[off1]);
    float4 t1 = __ldg(&s[off1]);

    __stcs(&out[row0 * (unsigned)VEC_PER_ROW + comp], soft_thresh4(v0, t0));
    __stcs(&out[row1 * (unsigned)VEC_PER_ROW + comp], soft_thresh4(v1, t1));
}

// ---------------------------------------------------------------- launch
extern "C" void kernel_launch(void* const* d_in, const int* in_sizes, int n_in,
                              void* d_out, int out_size) {
    const int4*   x4  = (const int4*)d_in[0];
    const float4* emb = (const float4*)d_in[1];
    const float4* s   = (const float4*)d_in[2];
    float4*       out = (float4*)d_out;

    k_hist   <<<NBLK, 1024>>>(x4);
    k_scanA  <<<NBUCKETS, 256>>>();
    k_scatter<<<NBLK, 1024>>>(x4);

    // ROWS/2 warps, 8 warps per 256-thread block
    k_gather<<<ROWS / 16, 256>>>(emb, s, out);
}